// round 1
// baseline (speedup 1.0000x reference)
#include <cuda_runtime.h>
#include <math.h>

#define BATCH 32
#define INCH 8
#define HH 96
#define WW 96
#define HWPIX (HH*WW)               // 9216
#define NPIX (BATCH*HWPIX)          // 294912
#define CSTRIDE HWPIX
#define BSTRIDE (INCH*HWPIX)
#define MIDD 128
#define HALF 4
#define TILE_P 64
#define NTHREADS 256
#define W2PITCH 132

// smem layout (in floats)
#define OFF_W2T   0                       // 128*132 = 16896
#define OFF_H     (OFF_W2T + 128*W2PITCH) // 16896
#define OFF_W1T   (OFF_H + 128*64)        // 25088  (4*132 = 528)
#define OFF_W3T   (OFF_W1T + 4*W2PITCH)   // 25616  (128*8 = 1024)
#define OFF_B1    (OFF_W3T + 128*8)       // 26640
#define OFF_B2    (OFF_B1 + 128)          // 26768
#define OFF_B3    (OFF_B2 + 128)          // 26896
#define OFF_X     (OFF_B3 + 16)           // 26912 (padded to keep 16B align)
#define OFF_ST    (OFF_X + 8*64)          // 27424
#define SMEM_FLOATS (OFF_ST + 8*64)       // 27936
#define SMEM_BYTES (SMEM_FLOATS*4)        // 111744

__constant__ int c_CI[4][4] = {{0,1,2,3},{4,5,6,7},{0,2,4,6},{1,3,5,7}};
__constant__ int c_FI[4][4] = {{4,5,6,7},{0,1,2,3},{1,3,5,7},{0,2,4,6}};

__device__ __forceinline__ float leaky(float v) {
    // max(v, 0.01v) == leaky_relu(v, 0.01) for all v
    return fmaxf(v, 0.01f * v);
}

__global__ void __launch_bounds__(NTHREADS, 2)
realnvp_kernel(const float* __restrict__ x,
               const float* __restrict__ W1, const float* __restrict__ b1,
               const float* __restrict__ W2, const float* __restrict__ b2,
               const float* __restrict__ W3, const float* __restrict__ b3,
               float* __restrict__ out)
{
    extern __shared__ float sm[];
    float* sW2t = sm + OFF_W2T;   // [k][o] pitch 132
    float* sH   = sm + OFF_H;     // [m][p] pitch 64
    float* sW1t = sm + OFF_W1T;   // [k][m] pitch 132
    float* sW3t = sm + OFF_W3T;   // [k][o] pitch 8
    float* sB1  = sm + OFF_B1;
    float* sB2  = sm + OFF_B2;
    float* sB3  = sm + OFF_B3;
    float* sX   = sm + OFF_X;     // [c][p] pitch 64
    float* sST  = sm + OFF_ST;    // [o][p] pitch 64

    const int tid = threadIdx.x;
    const int tile = blockIdx.x;
    const int gp0 = tile * TILE_P;
    const int b   = gp0 / HWPIX;      // TILE_P divides HWPIX -> no batch crossing
    const int hw0 = gp0 - b * HWPIX;

    // load x tile: [8][64]
    const float* xin = x + b * BSTRIDE + hw0;
    #pragma unroll
    for (int i = tid; i < 8 * TILE_P; i += NTHREADS) {
        int c = i >> 6, p = i & 63;
        sX[c * 64 + p] = xin[c * CSTRIDE + p];
    }

    const int px_t  = tid & 15;       // pixel group (4 px)
    const int mid_t = tid >> 4;       // mid group (8 outputs)
    const int m0 = mid_t * 8;
    const int p0 = px_t * 4;

    float ld_acc = 0.0f;              // log-det, valid for tid < 64

    for (int blk = 0; blk < 8; blk++) {
        const int pat = blk & 3;

        // ---- stage weights into smem ----
        {
            const float* W1g = W1 + blk * MIDD * HALF;
            #pragma unroll
            for (int i = tid; i < MIDD * HALF; i += NTHREADS) {
                int m = i >> 2, k = i & 3;
                sW1t[k * W2PITCH + m] = W1g[i];
            }
            if (tid < MIDD) {
                sB1[tid] = b1[blk * MIDD + tid];
                sB2[tid] = b2[blk * MIDD + tid];
            }
            if (tid < 8) sB3[tid] = b3[blk * 8 + tid];

            const float4* W2g4 = (const float4*)(W2 + blk * MIDD * MIDD);
            #pragma unroll
            for (int v = tid; v < MIDD * MIDD / 4; v += NTHREADS) {
                int o = v >> 5, kv = v & 31;
                float4 w = W2g4[v];
                float* d = &sW2t[(kv * 4) * W2PITCH + o];
                d[0]            = w.x;
                d[W2PITCH]      = w.y;
                d[2 * W2PITCH]  = w.z;
                d[3 * W2PITCH]  = w.w;
            }
            {   // W3: 8*128 = 1024 floats = 256 float4 (exactly one per thread)
                const float4* W3g4 = (const float4*)(W3 + blk * 8 * MIDD);
                int v = tid;
                int o = v >> 5, kv = v & 31;
                float4 w = W3g4[v];
                float* d = &sW3t[(kv * 4) * 8 + o];
                d[0]  = w.x;
                d[8]  = w.y;
                d[16] = w.z;
                d[24] = w.w;
            }
        }
        __syncthreads();

        // ---- stage 1: h1 = leaky(W1 @ x_fix + b1) ----
        float acc[4][8];
        #pragma unroll
        for (int j = 0; j < 8; j++) {
            float bb = sB1[m0 + j];
            #pragma unroll
            for (int p = 0; p < 4; p++) acc[p][j] = bb;
        }
        #pragma unroll
        for (int k = 0; k < 4; k++) {
            int fc = c_FI[pat][k];
            float4 xv = *(const float4*)&sX[fc * 64 + p0];
            float xp[4] = {xv.x, xv.y, xv.z, xv.w};
            const float* wr = &sW1t[k * W2PITCH + m0];
            float4 w0 = *(const float4*)wr;
            float4 w1 = *(const float4*)(wr + 4);
            float wv[8] = {w0.x, w0.y, w0.z, w0.w, w1.x, w1.y, w1.z, w1.w};
            #pragma unroll
            for (int p = 0; p < 4; p++)
                #pragma unroll
                for (int j = 0; j < 8; j++)
                    acc[p][j] = fmaf(xp[p], wv[j], acc[p][j]);
        }
        #pragma unroll
        for (int j = 0; j < 8; j++) {
            float4 hv;
            hv.x = leaky(acc[0][j]);
            hv.y = leaky(acc[1][j]);
            hv.z = leaky(acc[2][j]);
            hv.w = leaky(acc[3][j]);
            *(float4*)&sH[(m0 + j) * 64 + p0] = hv;
        }
        __syncthreads();

        // ---- stage 2: h2 = leaky(W2 @ h1 + b2) ----
        #pragma unroll
        for (int j = 0; j < 8; j++) {
            float bb = sB2[m0 + j];
            #pragma unroll
            for (int p = 0; p < 4; p++) acc[p][j] = bb;
        }
        #pragma unroll 4
        for (int k = 0; k < MIDD; k++) {
            float4 hv = *(const float4*)&sH[k * 64 + p0];
            float hp[4] = {hv.x, hv.y, hv.z, hv.w};
            const float* wr = &sW2t[k * W2PITCH + m0];
            float4 w0 = *(const float4*)wr;
            float4 w1 = *(const float4*)(wr + 4);
            float wv[8] = {w0.x, w0.y, w0.z, w0.w, w1.x, w1.y, w1.z, w1.w};
            #pragma unroll
            for (int p = 0; p < 4; p++)
                #pragma unroll
                for (int j = 0; j < 8; j++)
                    acc[p][j] = fmaf(hp[p], wv[j], acc[p][j]);
        }
        __syncthreads();   // all sH reads done before overwrite
        #pragma unroll
        for (int j = 0; j < 8; j++) {
            float4 hv;
            hv.x = leaky(acc[0][j]);
            hv.y = leaky(acc[1][j]);
            hv.z = leaky(acc[2][j]);
            hv.w = leaky(acc[3][j]);
            *(float4*)&sH[(m0 + j) * 64 + p0] = hv;
        }
        __syncthreads();

        // ---- stage 3: st = tanh(W3 @ h2 + b3) ----
        {
            int p  = tid & 63;
            int o2 = tid >> 6;            // 0..3 : this thread computes s-row o2 and t-row o2+4
            float sa = sB3[o2];
            float ta = sB3[o2 + 4];
            #pragma unroll 8
            for (int k = 0; k < MIDD; k++) {
                float h = sH[k * 64 + p];
                sa = fmaf(h, sW3t[k * 8 + o2],     sa);
                ta = fmaf(h, sW3t[k * 8 + o2 + 4], ta);
            }
            sST[o2 * 64 + p]       = tanhf(sa);
            sST[(o2 + 4) * 64 + p] = tanhf(ta);
        }
        __syncthreads();

        // ---- coupling update + log-det ----
        if (tid < 64) {
            int p = tid;
            #pragma unroll
            for (int j = 0; j < 4; j++) {
                float s = sST[j * 64 + p];
                float t = sST[(j + 4) * 64 + p];
                int c = c_CI[pat][j];
                float xc = sX[c * 64 + p];
                sX[c * 64 + p] = fmaf(xc, expf(s), t);
                ld_acc += s;
            }
        }
        __syncthreads();
    }

    // ---- write results ----
    float* outx = out + b * BSTRIDE + hw0;
    #pragma unroll
    for (int i = tid; i < 8 * TILE_P; i += NTHREADS) {
        int c = i >> 6, p = i & 63;
        outx[c * CSTRIDE + p] = sX[c * 64 + p];
    }
    if (tid < 64) {
        out[(size_t)INCH * NPIX + gp0 + tid] = ld_acc;
    }
}

extern "C" void kernel_launch(void* const* d_in, const int* in_sizes, int n_in,
                              void* d_out, int out_size) {
    const float* x  = (const float*)d_in[0];
    const float* W1 = (const float*)d_in[1];
    const float* b1 = (const float*)d_in[2];
    const float* W2 = (const float*)d_in[3];
    const float* b2 = (const float*)d_in[4];
    const float* W3 = (const float*)d_in[5];
    const float* b3 = (const float*)d_in[6];
    float* out = (float*)d_out;

    cudaFuncSetAttribute(realnvp_kernel,
                         cudaFuncAttributeMaxDynamicSharedMemorySize, SMEM_BYTES);

    dim3 grid(NPIX / TILE_P);   // 4608
    dim3 block(NTHREADS);
    realnvp_kernel<<<grid, block, SMEM_BYTES>>>(x, W1, b1, W2, b2, W3, b3, out);
}

// round 2
// speedup vs baseline: 1.0219x; 1.0219x over previous
#include <cuda_runtime.h>
#include <math.h>

typedef unsigned long long u64;

#define HWPIX 9216
#define NPIX 294912
#define CSTRIDE HWPIX
#define BSTRIDE (8*HWPIX)
#define TILE_P 128
#define NTHREADS 256
#define WPITCH 192              // 16 mid-blocks * 12 words, conflict-free phase reads

// smem layout (floats)
#define OFF_W2T 0                          // 128*192 = 24576
#define OFF_H   (OFF_W2T + 128*WPITCH)     // 24576 .. 128*128 = 16384
#define OFF_W1T (OFF_H + 128*128)          // 40960 .. 4*192 = 768
#define OFF_W3T (OFF_W1T + 4*WPITCH)       // 41728 .. 128*8 = 1024
#define OFF_B1  (OFF_W3T + 128*8)          // 42752
#define OFF_B2  (OFF_B1 + 128)             // 42880
#define OFF_B3  (OFF_B2 + 128)             // 43008
#define OFF_X   (OFF_B3 + 16)              // 43024 (16B aligned)
#define OFF_ST  (OFF_X + 8*128)            // 44048
#define SMEM_FLOATS (OFF_ST + 8*128)       // 45072
#define SMEM_BYTES (SMEM_FLOATS*4)         // 180288

__constant__ int c_CI[4][4] = {{0,1,2,3},{4,5,6,7},{0,2,4,6},{1,3,5,7}};
__constant__ int c_FI[4][4] = {{4,5,6,7},{0,1,2,3},{1,3,5,7},{0,2,4,6}};

__device__ __forceinline__ u64 pk2(float a, float b){
    u64 r; asm("mov.b64 %0,{%1,%2};" : "=l"(r) : "f"(a), "f"(b)); return r;
}
__device__ __forceinline__ void upk2(u64 v, float& a, float& b){
    asm("mov.b64 {%0,%1},%2;" : "=f"(a), "=f"(b) : "l"(v));
}
__device__ __forceinline__ void fma2(u64& d, u64 a, u64 b){
    asm("fma.rn.f32x2 %0,%1,%2,%0;" : "+l"(d) : "l"(a), "l"(b));
}
__device__ __forceinline__ float leaky(float v){ return fmaxf(v, 0.01f * v); }
__device__ __forceinline__ float fast_tanh(float v){
    // 1 - 2/(e^{2v}+1): exact limits at +/-inf, ~1e-7 rel err via MUFU.EX2
    float e = __expf(2.0f * v);
    return 1.0f - __fdividef(2.0f, e + 1.0f);
}

__global__ void __launch_bounds__(NTHREADS, 1)
realnvp_kernel(const float* __restrict__ x,
               const float* __restrict__ W1, const float* __restrict__ b1,
               const float* __restrict__ W2, const float* __restrict__ b2,
               const float* __restrict__ W3, const float* __restrict__ b3,
               float* __restrict__ out)
{
    extern __shared__ float sm[];
    float* sW2t = sm + OFF_W2T;   // [k][block-strided o]
    float* sH   = sm + OFF_H;     // [m][rot(p)] pitch 128
    float* sW1t = sm + OFF_W1T;
    float* sW3t = sm + OFF_W3T;   // [k][o] pitch 8
    float* sB1  = sm + OFF_B1;
    float* sB2  = sm + OFF_B2;
    float* sB3  = sm + OFF_B3;
    float* sX   = sm + OFF_X;     // [c][p] pitch 128
    float* sST  = sm + OFF_ST;    // [o][p] pitch 128

    const int tid = threadIdx.x;
    const int gp0 = blockIdx.x * TILE_P;
    const int b   = gp0 / HWPIX;           // 128 | 9216 -> no batch crossing
    const int hw0 = gp0 - b * HWPIX;

    // warp remap: phase (8 lanes) = 8 mid-groups x 1 px-group (x-reads broadcast)
    const int mid_t = (tid & 7) | (((tid >> 5) & 1) << 3);   // 0..15
    const int px_t  = ((tid >> 3) & 3) | ((tid >> 6) << 2);  // 0..15
    const int m0 = mid_t * 8;
    const int p0 = px_t * 8;
    const int my_rot = (mid_t & 7) << 2;   // store rotation for rows m0..m0+7

    // load x tile [8][128] (one float4 per thread)
    {
        const float* xin = x + (size_t)b * BSTRIDE + hw0;
        int c = tid >> 5, p4 = (tid & 31) << 2;
        *(float4*)&sX[c * 128 + p4] = *(const float4*)&xin[c * CSTRIDE + p4];
    }

    float ld_acc = 0.0f;   // valid for tid < 128

    for (int blk = 0; blk < 8; blk++) {
        const int pat = blk & 3;

        // ---------- stage weights ----------
        {
            const float* W1g = W1 + blk * 512;
            #pragma unroll
            for (int i = tid; i < 512; i += NTHREADS) {
                int m = i >> 2, k = i & 3;
                sW1t[k * WPITCH + (m >> 3) * 12 + (m & 7)] = W1g[i];
            }
            if (tid < 128) { sB1[tid] = b1[blk * 128 + tid]; sB2[tid] = b2[blk * 128 + tid]; }
            if (tid < 8)   sB3[tid] = b3[blk * 8 + tid];

            const float4* W2g4 = (const float4*)(W2 + blk * 16384);
            #pragma unroll
            for (int v = tid; v < 4096; v += NTHREADS) {
                int o = v >> 5, kv = v & 31;
                float4 w = W2g4[v];
                float* d = &sW2t[(kv * 4) * WPITCH + (o >> 3) * 12 + (o & 7)];
                d[0] = w.x; d[WPITCH] = w.y; d[2*WPITCH] = w.z; d[3*WPITCH] = w.w;
            }
            {   // W3: 8x128 floats = 256 float4, exactly 1/thread
                const float4* W3g4 = (const float4*)(W3 + blk * 1024);
                int v = tid, o = v >> 5, kv = v & 31;
                float4 w = W3g4[v];
                float* d = &sW3t[(kv * 4) * 8 + o];
                d[0] = w.x; d[8] = w.y; d[16] = w.z; d[24] = w.w;
            }
        }
        __syncthreads();

        u64 acc[4][8];

        // ---------- stage 1: h1 = leaky(W1 @ x_fix + b1), K=4 ----------
        #pragma unroll
        for (int j = 0; j < 8; j++) {
            float bb = sB1[m0 + j]; u64 bp = pk2(bb, bb);
            #pragma unroll
            for (int p = 0; p < 4; p++) acc[p][j] = bp;
        }
        #pragma unroll
        for (int k = 0; k < 4; k++) {
            int fc = c_FI[pat][k];
            const float* xr = &sX[fc * 128 + p0];
            ulonglong2 xa = *(const ulonglong2*)xr;
            ulonglong2 xb = *(const ulonglong2*)(xr + 4);
            u64 xp[4] = {xa.x, xa.y, xb.x, xb.y};
            const float4* wr = (const float4*)&sW1t[k * WPITCH + mid_t * 12];
            float4 w0 = wr[0], w1 = wr[1];
            u64 wd[8] = {pk2(w0.x,w0.x), pk2(w0.y,w0.y), pk2(w0.z,w0.z), pk2(w0.w,w0.w),
                         pk2(w1.x,w1.x), pk2(w1.y,w1.y), pk2(w1.z,w1.z), pk2(w1.w,w1.w)};
            #pragma unroll
            for (int p = 0; p < 4; p++)
                #pragma unroll
                for (int j = 0; j < 8; j++) fma2(acc[p][j], xp[p], wd[j]);
        }
        #pragma unroll
        for (int j = 0; j < 8; j++) {
            int r = m0 + j;
            int c0 = (p0 + my_rot) & 127, c1 = (p0 + 4 + my_rot) & 127;
            float4 lo, hi;
            upk2(acc[0][j], lo.x, lo.y); upk2(acc[1][j], lo.z, lo.w);
            upk2(acc[2][j], hi.x, hi.y); upk2(acc[3][j], hi.z, hi.w);
            lo.x = leaky(lo.x); lo.y = leaky(lo.y); lo.z = leaky(lo.z); lo.w = leaky(lo.w);
            hi.x = leaky(hi.x); hi.y = leaky(hi.y); hi.z = leaky(hi.z); hi.w = leaky(hi.w);
            *(float4*)&sH[r * 128 + c0] = lo;
            *(float4*)&sH[r * 128 + c1] = hi;
        }
        __syncthreads();

        // ---------- stage 2: h2 = leaky(W2 @ h1 + b2), K=128 ----------
        #pragma unroll
        for (int j = 0; j < 8; j++) {
            float bb = sB2[m0 + j]; u64 bp = pk2(bb, bb);
            #pragma unroll
            for (int p = 0; p < 4; p++) acc[p][j] = bp;
        }
        #pragma unroll 2
        for (int k = 0; k < 128; k++) {
            int rot = ((k >> 3) & 7) << 2;
            int c0 = (p0 + rot) & 127, c1 = (p0 + 4 + rot) & 127;
            const float* hr = &sH[k * 128];
            ulonglong2 xa = *(const ulonglong2*)(hr + c0);
            ulonglong2 xb = *(const ulonglong2*)(hr + c1);
            u64 xp[4] = {xa.x, xa.y, xb.x, xb.y};
            const float4* wr = (const float4*)&sW2t[k * WPITCH + mid_t * 12];
            float4 w0 = wr[0], w1 = wr[1];
            u64 wd[8] = {pk2(w0.x,w0.x), pk2(w0.y,w0.y), pk2(w0.z,w0.z), pk2(w0.w,w0.w),
                         pk2(w1.x,w1.x), pk2(w1.y,w1.y), pk2(w1.z,w1.z), pk2(w1.w,w1.w)};
            #pragma unroll
            for (int p = 0; p < 4; p++)
                #pragma unroll
                for (int j = 0; j < 8; j++) fma2(acc[p][j], xp[p], wd[j]);
        }
        __syncthreads();   // all h1 reads done before overwrite
        #pragma unroll
        for (int j = 0; j < 8; j++) {
            int r = m0 + j;
            int c0 = (p0 + my_rot) & 127, c1 = (p0 + 4 + my_rot) & 127;
            float4 lo, hi;
            upk2(acc[0][j], lo.x, lo.y); upk2(acc[1][j], lo.z, lo.w);
            upk2(acc[2][j], hi.x, hi.y); upk2(acc[3][j], hi.z, hi.w);
            lo.x = leaky(lo.x); lo.y = leaky(lo.y); lo.z = leaky(lo.z); lo.w = leaky(lo.w);
            hi.x = leaky(hi.x); hi.y = leaky(hi.y); hi.z = leaky(hi.z); hi.w = leaky(hi.w);
            *(float4*)&sH[r * 128 + c0] = lo;
            *(float4*)&sH[r * 128 + c1] = hi;
        }
        __syncthreads();

        // ---------- stage 3: st = tanh(W3 @ h2 + b3), 8 outputs ----------
        {
            int pp = tid & 63;       // pixel pair
            int oq = tid >> 6;       // 0..3: s-row oq, t-row oq+4
            u64 sa = pk2(sB3[oq], sB3[oq]);
            u64 ta = pk2(sB3[oq + 4], sB3[oq + 4]);
            #pragma unroll 4
            for (int k = 0; k < 128; k++) {
                int cc = (2 * pp + (((k >> 3) & 7) << 2)) & 127;
                u64 hp = *(const u64*)&sH[k * 128 + cc];
                float ws = sW3t[k * 8 + oq];
                float wt = sW3t[k * 8 + oq + 4];
                fma2(sa, hp, pk2(ws, ws));
                fma2(ta, hp, pk2(wt, wt));
            }
            float s0, s1, t0, t1;
            upk2(sa, s0, s1); upk2(ta, t0, t1);
            *(u64*)&sST[oq * 128 + 2 * pp]       = pk2(fast_tanh(s0), fast_tanh(s1));
            *(u64*)&sST[(oq + 4) * 128 + 2 * pp] = pk2(fast_tanh(t0), fast_tanh(t1));
        }
        __syncthreads();

        // ---------- coupling update + log-det ----------
        if (tid < 128) {
            int p = tid;
            #pragma unroll
            for (int j = 0; j < 4; j++) {
                float s = sST[j * 128 + p];
                float t = sST[(j + 4) * 128 + p];
                int c = c_CI[pat][j];
                float xc = sX[c * 128 + p];
                sX[c * 128 + p] = fmaf(xc, __expf(s), t);
                ld_acc += s;
            }
        }
        __syncthreads();
    }

    // ---------- write results ----------
    {
        float* outx = out + (size_t)b * BSTRIDE + hw0;
        int c = tid >> 5, p4 = (tid & 31) << 2;
        *(float4*)&outx[c * CSTRIDE + p4] = *(const float4*)&sX[c * 128 + p4];
    }
    if (tid < 128) {
        out[(size_t)8 * NPIX + gp0 + tid] = ld_acc;
    }
}

extern "C" void kernel_launch(void* const* d_in, const int* in_sizes, int n_in,
                              void* d_out, int out_size) {
    const float* x  = (const float*)d_in[0];
    const float* W1 = (const float*)d_in[1];
    const float* b1 = (const float*)d_in[2];
    const float* W2 = (const float*)d_in[3];
    const float* b2 = (const float*)d_in[4];
    const float* W3 = (const float*)d_in[5];
    const float* b3 = (const float*)d_in[6];
    float* out = (float*)d_out;

    cudaFuncSetAttribute(realnvp_kernel,
                         cudaFuncAttributeMaxDynamicSharedMemorySize, SMEM_BYTES);

    dim3 grid(NPIX / TILE_P);   // 2304
    dim3 block(NTHREADS);
    realnvp_kernel<<<grid, block, SMEM_BYTES>>>(x, W1, b1, W2, b2, W3, b3, out);
}

// round 3
// speedup vs baseline: 1.5573x; 1.5239x over previous
#include <cuda_runtime.h>
#include <math.h>

typedef unsigned long long u64;

#define HWPIX 9216
#define NPIX 294912
#define CSTRIDE HWPIX
#define BSTRIDE (8*HWPIX)
#define TILE_P 128
#define NTHREADS 512

// smem offsets (floats)
#define OFF_W2 0                      // 128*128
#define OFF_H  (OFF_W2 + 128*128)     // 128*128
#define OFF_W1 (OFF_H + 128*128)      // 4*128
#define OFF_W3 (OFF_W1 + 4*128)       // 8*128 natural [o][k]
#define OFF_B1 (OFF_W3 + 8*128)
#define OFF_B2 (OFF_B1 + 128)
#define OFF_B3 (OFF_B2 + 128)
#define OFF_X  (OFF_B3 + 16)          // 8*128
#define OFF_ST (OFF_X + 8*128)        // 8*128
#define SMEM_FLOATS (OFF_ST + 8*128)  // 36624
#define SMEM_BYTES (SMEM_FLOATS*4)    // 146496

__constant__ int c_CI[4][4] = {{0,1,2,3},{4,5,6,7},{0,2,4,6},{1,3,5,7}};
__constant__ int c_FI[4][4] = {{4,5,6,7},{0,1,2,3},{1,3,5,7},{0,2,4,6}};

__device__ __forceinline__ u64 pk2(float a, float b){
    u64 r; asm("mov.b64 %0,{%1,%2};" : "=l"(r) : "f"(a), "f"(b)); return r;
}
__device__ __forceinline__ void upk2(u64 v, float& a, float& b){
    asm("mov.b64 {%0,%1},%2;" : "=f"(a), "=f"(b) : "l"(v));
}
__device__ __forceinline__ void fma2(u64& d, u64 a, u64 b){
    asm("fma.rn.f32x2 %0,%1,%2,%0;" : "+l"(d) : "l"(a), "l"(b));
}
__device__ __forceinline__ float leaky(float v){ return fmaxf(v, 0.01f * v); }
__device__ __forceinline__ float fast_tanh(float v){
    float e = __expf(2.0f * v);
    return 1.0f - __fdividef(2.0f, e + 1.0f);
}

__global__ void __launch_bounds__(NTHREADS, 1)
realnvp_kernel(const float* __restrict__ x,
               const float* __restrict__ W1, const float* __restrict__ b1,
               const float* __restrict__ W2, const float* __restrict__ b2,
               const float* __restrict__ W3, const float* __restrict__ b3,
               float* __restrict__ out)
{
    extern __shared__ float sm[];
    float* sW2 = sm + OFF_W2;   // [k][o ^ s(k)], s(k)=((k>>2)&7)<<2
    float* sH  = sm + OFF_H;    // [k][p ^ s(k)]
    float* sW1 = sm + OFF_W1;   // [k][m] natural (k<4 -> s=0)
    float* sW3 = sm + OFF_W3;   // [o][k] natural
    float* sB1 = sm + OFF_B1;
    float* sB2 = sm + OFF_B2;
    float* sB3 = sm + OFF_B3;
    float* sX  = sm + OFF_X;    // [c][p] pitch 128
    float* sST = sm + OFF_ST;   // [o][p] pitch 128

    const int tid  = threadIdx.x;
    const int lane = tid & 31, wrp = tid >> 5;
    const int mid_t = (lane & 7) | ((wrp & 3) << 3);   // 0..31
    const int px_t  = (lane >> 3) | ((wrp >> 2) << 2); // 0..15
    const int m0 = mid_t * 4;      // 4 consecutive mids
    const int p0 = px_t * 8;       // 8 consecutive pixels
    const int tm = (mid_t & 7) << 2;  // store swizzle for rows m0..m0+3

    const int gp0 = blockIdx.x * TILE_P;
    const int b   = gp0 / HWPIX;
    const int hw0 = gp0 - b * HWPIX;

    // load x tile [8][128]
    {
        const float* xin = x + (size_t)b * BSTRIDE + hw0;
        int c = tid >> 6, p2 = (tid & 63) << 1;
        *(float2*)&sX[c * 128 + p2] = *(const float2*)&xin[c * CSTRIDE + p2];
    }

    float ld_acc = 0.0f;   // valid for tid < 128

    for (int blk = 0; blk < 8; blk++) {
        const int pat = blk & 3;

        // ---------- stage weights ----------
        {
            const float4* W2g = (const float4*)(W2 + blk * 16384);
            #pragma unroll
            for (int it = 0; it < 8; it++) {
                int v = tid + it * NTHREADS;
                int o = v >> 5, kv = v & 31;        // coalesced LDG
                float4 wv = W2g[v];
                int col = o ^ ((kv & 7) << 2);      // swizzled, rows 4kv..4kv+3
                float* d = sW2 + (kv * 4) * 128 + col;
                d[0] = wv.x; d[128] = wv.y; d[256] = wv.z; d[384] = wv.w;
            }
            if (tid < 128) {
                float4 wv = ((const float4*)(W1 + blk * 512))[tid];
                sW1[0 * 128 + tid] = wv.x;
                sW1[1 * 128 + tid] = wv.y;
                sW1[2 * 128 + tid] = wv.z;
                sW1[3 * 128 + tid] = wv.w;
                sB1[tid] = b1[blk * 128 + tid];
                sB2[tid] = b2[blk * 128 + tid];
            } else if (tid < 384) {
                ((float4*)sW3)[tid - 128] = ((const float4*)(W3 + blk * 1024))[tid - 128];
            } else if (tid < 392) {
                sB3[tid - 384] = b3[blk * 8 + (tid - 384)];
            }
        }
        __syncthreads();

        u64 acc[4][4];   // [px-pair][mid j]

        // ---------- stage 1: h1 = leaky(W1 @ x_fix + b1), K=4 ----------
        #pragma unroll
        for (int j = 0; j < 4; j++) {
            float bb = sB1[m0 + j]; u64 bp = pk2(bb, bb);
            #pragma unroll
            for (int p = 0; p < 4; p++) acc[p][j] = bp;
        }
        #pragma unroll
        for (int k = 0; k < 4; k++) {
            int fc = c_FI[pat][k];
            ulonglong2 ha = *(const ulonglong2*)&sX[fc * 128 + p0];
            ulonglong2 hb = *(const ulonglong2*)&sX[fc * 128 + p0 + 4];
            u64 xp[4] = {ha.x, ha.y, hb.x, hb.y};
            float4 wv = *(const float4*)&sW1[k * 128 + m0];
            u64 wd[4] = {pk2(wv.x,wv.x), pk2(wv.y,wv.y), pk2(wv.z,wv.z), pk2(wv.w,wv.w)};
            #pragma unroll
            for (int p = 0; p < 4; p++)
                #pragma unroll
                for (int j = 0; j < 4; j++) fma2(acc[p][j], xp[p], wd[j]);
        }
        #pragma unroll
        for (int j = 0; j < 4; j++) {
            int r = m0 + j;
            float4 lo, hi;
            upk2(acc[0][j], lo.x, lo.y); upk2(acc[1][j], lo.z, lo.w);
            upk2(acc[2][j], hi.x, hi.y); upk2(acc[3][j], hi.z, hi.w);
            lo.x = leaky(lo.x); lo.y = leaky(lo.y); lo.z = leaky(lo.z); lo.w = leaky(lo.w);
            hi.x = leaky(hi.x); hi.y = leaky(hi.y); hi.z = leaky(hi.z); hi.w = leaky(hi.w);
            *(float4*)&sH[r * 128 + (p0 ^ tm)]       = lo;
            *(float4*)&sH[r * 128 + ((p0 + 4) ^ tm)] = hi;
        }
        __syncthreads();

        // ---------- stage 2: h2 = leaky(W2 @ h1 + b2), K=128 ----------
        #pragma unroll
        for (int j = 0; j < 4; j++) {
            float bb = sB2[m0 + j]; u64 bp = pk2(bb, bb);
            #pragma unroll
            for (int p = 0; p < 4; p++) acc[p][j] = bp;
        }
        #pragma unroll 2
        for (int kk = 0; kk < 32; kk++) {
            const int tk = (kk & 7) << 2;
            const float* hb = sH  + kk * 512;
            const float* wb = sW2 + kk * 512;
            const int hc0 = p0 ^ tk;
            const int hc1 = (p0 + 4) ^ tk;
            const int wc  = m0 ^ tk;
            #pragma unroll
            for (int i = 0; i < 4; i++) {
                ulonglong2 ha = *(const ulonglong2*)(hb + i * 128 + hc0);
                ulonglong2 hv = *(const ulonglong2*)(hb + i * 128 + hc1);
                u64 xp[4] = {ha.x, ha.y, hv.x, hv.y};
                float4 wv = *(const float4*)(wb + i * 128 + wc);
                u64 wd[4] = {pk2(wv.x,wv.x), pk2(wv.y,wv.y), pk2(wv.z,wv.z), pk2(wv.w,wv.w)};
                #pragma unroll
                for (int p = 0; p < 4; p++)
                    #pragma unroll
                    for (int j = 0; j < 4; j++) fma2(acc[p][j], xp[p], wd[j]);
            }
        }
        __syncthreads();   // all h1 reads done before overwrite
        #pragma unroll
        for (int j = 0; j < 4; j++) {
            int r = m0 + j;
            float4 lo, hi;
            upk2(acc[0][j], lo.x, lo.y); upk2(acc[1][j], lo.z, lo.w);
            upk2(acc[2][j], hi.x, hi.y); upk2(acc[3][j], hi.z, hi.w);
            lo.x = leaky(lo.x); lo.y = leaky(lo.y); lo.z = leaky(lo.z); lo.w = leaky(lo.w);
            hi.x = leaky(hi.x); hi.y = leaky(hi.y); hi.z = leaky(hi.z); hi.w = leaky(hi.w);
            *(float4*)&sH[r * 128 + (p0 ^ tm)]       = lo;
            *(float4*)&sH[r * 128 + ((p0 + 4) ^ tm)] = hi;
        }
        __syncthreads();

        // ---------- stage 3: st = tanh(W3 @ h2 + b3) ----------
        {
            int pp = tid & 63;     // pixel pair
            int oq = tid >> 6;     // 0..7, warp-uniform
            float bb = sB3[oq];
            u64 a = pk2(bb, bb);
            const float* w3r = sW3 + oq * 128;
            #pragma unroll 4
            for (int kk = 0; kk < 32; kk++) {
                int col = (2 * pp) ^ ((kk & 7) << 2);
                const float* hb = sH + kk * 512 + col;
                #pragma unroll
                for (int i = 0; i < 4; i++) {
                    u64 hp = *(const u64*)(hb + i * 128);
                    float wv = w3r[kk * 4 + i];
                    fma2(a, hp, pk2(wv, wv));
                }
            }
            float s0, s1; upk2(a, s0, s1);
            *(u64*)&sST[oq * 128 + 2 * pp] = pk2(fast_tanh(s0), fast_tanh(s1));
        }
        __syncthreads();

        // ---------- coupling update + log-det ----------
        if (tid < 128) {
            int p = tid;
            #pragma unroll
            for (int j = 0; j < 4; j++) {
                float s = sST[j * 128 + p];
                float t = sST[(j + 4) * 128 + p];
                int c = c_CI[pat][j];
                float xc = sX[c * 128 + p];
                sX[c * 128 + p] = fmaf(xc, __expf(s), t);
                ld_acc += s;
            }
        }
        __syncthreads();
    }

    // ---------- write results ----------
    {
        float* outx = out + (size_t)b * BSTRIDE + hw0;
        int c = tid >> 6, p2 = (tid & 63) << 1;
        *(float2*)&outx[c * CSTRIDE + p2] = *(const float2*)&sX[c * 128 + p2];
    }
    if (tid < 128) {
        out[(size_t)8 * NPIX + gp0 + tid] = ld_acc;
    }
}

extern "C" void kernel_launch(void* const* d_in, const int* in_sizes, int n_in,
                              void* d_out, int out_size) {
    const float* x  = (const float*)d_in[0];
    const float* W1 = (const float*)d_in[1];
    const float* b1 = (const float*)d_in[2];
    const float* W2 = (const float*)d_in[3];
    const float* b2 = (const float*)d_in[4];
    const float* W3 = (const float*)d_in[5];
    const float* b3 = (const float*)d_in[6];
    float* out = (float*)d_out;

    cudaFuncSetAttribute(realnvp_kernel,
                         cudaFuncAttributeMaxDynamicSharedMemorySize, SMEM_BYTES);

    dim3 grid(NPIX / TILE_P);   // 2304
    dim3 block(NTHREADS);
    realnvp_kernel<<<grid, block, SMEM_BYTES>>>(x, W1, b1, W2, b2, W3, b3, out);
}